// round 8
// baseline (speedup 1.0000x reference)
#include <cuda_runtime.h>
#include <cuda_bf16.h>
#include <cfloat>
#include <cstdint>

// LossFun: loss = -sum over (b,l) of [argmax_v(scores)==target] * w * log(max score) / B
// scores: [B, L, V] float32, targets: [B, L] int32. B=8, L=2048, V=32000.
//
// Single streaming kernel, CTA per row. FMNMX-tree fast path for the scan
// (tile max via single-instruction fmaxf), rare index-resolution slow path
// only when the running best improves (~ln(#tiles) per thread). Strict '>'
// update + in-order resolution preserves argmax first-index tiebreak.
//
// Matching CTAs atomicAdd the float term -w*log(picked)/B directly into
// d_out (zeroed by a memset node). ~8200 near-equal-magnitude terms ->
// random-order fp32 atomic sum error ~5e-6 relative, well under 1e-3.
// Accurate logf is required: picked ~ (1 - 3e-5), so log(picked) ~ -3e-5
// and __logf's absolute error near 1 would be ~3e-3 relative.

static constexpr int V_DIM  = 32000;
static constexpr float INV_B = 0.125f;   // 1/8
static constexpr float BETA  = 2.0f;

__device__ __forceinline__ void tile_update(const float4& v, int base,
                                            int& bidx, float m)
{
    if (v.x == m && base + 0 < bidx) { bidx = base + 0; return; }
    if (v.y == m && base + 1 < bidx) { bidx = base + 1; return; }
    if (v.z == m && base + 2 < bidx) { bidx = base + 2; return; }
    if (v.w == m && base + 3 < bidx) { bidx = base + 3; return; }
}

__global__ __launch_bounds__(256, 4)
void lossfun_argmax_kernel(const float* __restrict__ scores,
                           const int* __restrict__ targets,
                           float* __restrict__ out)
{
    const int tid = threadIdx.x;
    const int row = blockIdx.x;
    const float4* __restrict__ p =
        reinterpret_cast<const float4*>(scores + (size_t)row * V_DIM);

    float best = -FLT_MAX;
    int   bidx = 0x7FFFFFFF;

    // Main loop: 7 iterations x 4 coalesced float4 loads = 7168 vec4.
    #pragma unroll
    for (int k = 0; k < 7; k++) {
        const int i = tid + k * 1024;
        float4 a = __ldg(p + i);
        float4 b = __ldg(p + i + 256);
        float4 c = __ldg(p + i + 512);
        float4 d = __ldg(p + i + 768);

        float ma = fmaxf(fmaxf(a.x, a.y), fmaxf(a.z, a.w));
        float mb = fmaxf(fmaxf(b.x, b.y), fmaxf(b.z, b.w));
        float mc = fmaxf(fmaxf(c.x, c.y), fmaxf(c.z, c.w));
        float md = fmaxf(fmaxf(d.x, d.y), fmaxf(d.z, d.w));
        float m  = fmaxf(fmaxf(ma, mb), fmaxf(mc, md));

        if (m > best) {                 // rare: ~ln(#tiles) per thread
            best = m;
            bidx = 0x7FFFFFFF;
            if      (ma == m) tile_update(a, (i)          << 2, bidx, m);
            if (bidx == 0x7FFFFFFF && mb == m) tile_update(b, (i + 256) << 2, bidx, m);
            if (bidx == 0x7FFFFFFF && mc == m) tile_update(c, (i + 512) << 2, bidx, m);
            if (bidx == 0x7FFFFFFF && md == m) tile_update(d, (i + 768) << 2, bidx, m);
        }
    }

    // Epilogue: vec4 indices 7168..7999 (832 = 3*256 + 64).
    {
        const int i1 = 7168 + tid;
        const int i2 = 7424 + tid;
        const int i3 = 7680 + tid;
        float4 a = __ldg(p + i1);
        float4 b = __ldg(p + i2);
        float4 c = __ldg(p + i3);

        float ma = fmaxf(fmaxf(a.x, a.y), fmaxf(a.z, a.w));
        float mb = fmaxf(fmaxf(b.x, b.y), fmaxf(b.z, b.w));
        float mc = fmaxf(fmaxf(c.x, c.y), fmaxf(c.z, c.w));
        float m  = fmaxf(fmaxf(ma, mb), mc);

        if (m > best) {
            best = m;
            bidx = 0x7FFFFFFF;
            if      (ma == m) tile_update(a, i1 << 2, bidx, m);
            if (bidx == 0x7FFFFFFF && mb == m) tile_update(b, i2 << 2, bidx, m);
            if (bidx == 0x7FFFFFFF && mc == m) tile_update(c, i3 << 2, bidx, m);
        }

        if (tid < 64) {
            const int i4 = 7936 + tid;
            float4 d = __ldg(p + i4);
            float md = fmaxf(fmaxf(d.x, d.y), fmaxf(d.z, d.w));
            if (md > best) {
                best = md;
                bidx = 0x7FFFFFFF;
                tile_update(d, i4 << 2, bidx, md);
            }
        }
    }

    // Warp reduce (value-max, lowest index on tie)
    #pragma unroll
    for (int o = 16; o > 0; o >>= 1) {
        float ov = __shfl_down_sync(0xFFFFFFFFu, best, o);
        int   oi = __shfl_down_sync(0xFFFFFFFFu, bidx, o);
        if (ov > best || (ov == best && oi < bidx)) { best = ov; bidx = oi; }
    }

    __shared__ float sv[8];
    __shared__ int   si[8];
    const int lane = tid & 31;
    const int wid  = tid >> 5;
    if (lane == 0) { sv[wid] = best; si[wid] = bidx; }
    __syncthreads();

    if (tid == 0) {
        float fb = sv[0]; int fi = si[0];
        #pragma unroll
        for (int w = 1; w < 8; w++) {
            float ov = sv[w]; int oi = si[w];
            if (ov > fb || (ov == fb && oi < fi)) { fb = ov; fi = oi; }
        }
        int tgt = __ldg(targets + row);
        if (fi == tgt) {
            float w = (tgt == 0) ? 1.0f : BETA;
            atomicAdd(out, -w * logf(fb) * INV_B);
        }
    }
}

extern "C" void kernel_launch(void* const* d_in, const int* in_sizes, int n_in,
                              void* d_out, int out_size)
{
    const float* scores  = (const float*)d_in[0];
    const int*   targets = (const int*)d_in[1];
    float*       out     = (float*)d_out;

    const int rows = in_sizes[1];   // B * L = 16384

    cudaMemsetAsync(out, 0, sizeof(float));
    lossfun_argmax_kernel<<<rows, 256>>>(scores, targets, out);
}